// round 9
// baseline (speedup 1.0000x reference)
#include <cuda_runtime.h>
#include <math.h>

#define BATCH 128
#define CTX 64
#define HID 128
#define KSLICES 19            // 9 time + 9 dist + 1 hidden
#define KTOT (KSLICES*128)    // 2432

typedef unsigned long long u64;

// Scratch (__device__ globals: allocation-free rule)
__device__ float g_Xagg[BATCH * KTOT];             // [b][k] row-major
__device__ float g_gpart[KSLICES * BATCH * HID];   // per-slice GEMM partials
__device__ unsigned g_tilecnt[8];                  // monotonic arrival counters

// ---- packed f32x2 helpers --------------------------------------------------
__device__ __forceinline__ u64 pack2(float v) {
    u64 r; asm("mov.b64 %0, {%1, %1};" : "=l"(r) : "f"(v)); return r;
}
__device__ __forceinline__ void ffma2(u64& d, u64 a, u64 b) {
    asm("fma.rn.f32x2 %0, %1, %2, %0;" : "+l"(d) : "l"(a), "l"(b));
}
__device__ __forceinline__ u64 fadd2(u64 a, u64 b) {
    u64 r; asm("add.rn.f32x2 %0, %1, %2;" : "=l"(r) : "l"(a), "l"(b)); return r;
}

// ---------------------------------------------------------------------------
// K1: per-batch slot aggregation  acc[18][128] = sel[18][64] @ x[64][128]
//   grid = 128 (batch), 512 threads = 8 ctx-groups x 64 dim-pairs.
//   dynamic smem: sel2 9216B + red[8] 73728B = 82944B. Coalesced [b][k] store.
// ---------------------------------------------------------------------------
#define K1_SMEM (9216 + 73728)
__global__ __launch_bounds__(512, 1)
void k1_aggregate(const float* __restrict__ x,     // [B][CTX][128]
                  const int* __restrict__ timec,   // [B][CTX]
                  const int* __restrict__ distc,   // [B][CTX]
                  const void* __restrict__ maskp,  // [B][CTX] int32 OR bytes
                  const float* __restrict__ h)     // [B][128]
{
    extern __shared__ __align__(16) char smraw[];
    u64*   sel2 = (u64*)smraw;                 // [c][s] : c*18+s
    float* red  = (float*)(smraw + 9216);      // [g][i] : g*2304+i
    __shared__ int s_flag;

    const int b   = blockIdx.x;
    const int tid = threadIdx.x;
    const int g   = tid >> 6;   // ctx group: c in [8g, 8g+8)
    const int q   = tid & 63;   // dim pair:  dims 2q, 2q+1

    // ---- front-issue ALL global loads (one latency round trip) ----
    u64 xv[8];
    {
        const float* xb = x + (size_t)b * CTX * 128 + q * 2;
        #pragma unroll
        for (int cc = 0; cc < 8; cc++)
            xv[cc] = *(const u64*)(xb + (g * 8 + cc) * 128);
    }
    // mask dtype sniff: 512 words (in-bounds under both layouts)
    unsigned sniffw = ((const unsigned*)maskp)[tid];
    int t_ = 0, d_ = 0; unsigned m_int = 0; unsigned char m_byte = 0;
    float hv = 0.0f;
    if (tid < 128) {
        int c = tid & 63;
        t_ = timec[b * CTX + c];
        d_ = distc[b * CTX + c];
        m_int  = ((const unsigned*)maskp)[b * CTX + c];
        m_byte = ((const unsigned char*)maskp)[b * CTX + c];
        hv = h[b * HID + tid];
    }

    if (tid == 0) s_flag = 0;
    __syncthreads();
    if (sniffw > 1u) atomicOr(&s_flag, 1);
    __syncthreads();
    const int byte_layout = s_flag;

    // sel2[c][s] = (slot==s) ? (0.5*mask, 0.5*mask) : 0
    if (tid < 128) {
        int c = tid & 63, hf = tid >> 6;
        int m = byte_layout ? (m_byte != 0) : (m_int != 0);
        float w = m ? 0.5f : 0.0f;
        int idx = hf ? d_ : t_;
        u64 wp = pack2(w);
        #pragma unroll
        for (int s = 0; s < 9; s++)
            sel2[c * 18 + hf * 9 + s] = (idx == s) ? wp : 0ull;
    }
    __syncthreads();

    u64 acc[18];
    #pragma unroll
    for (int s = 0; s < 18; s++) acc[s] = 0ull;

    #pragma unroll
    for (int cc = 0; cc < 8; cc++) {
        int c = g * 8 + cc;
        u64 xc = xv[cc];
        #pragma unroll
        for (int s = 0; s < 18; s++)
            ffma2(acc[s], sel2[c * 18 + s], xc);   // LDS.64 bcast + FFMA2
    }

    #pragma unroll
    for (int s = 0; s < 18; s++)
        *(u64*)&red[g * 2304 + s * 128 + q * 2] = acc[s];
    __syncthreads();

    // fold 8 groups as u64 pairs, coalesced STG.64 into g_Xagg[b][k]
    u64* dstrow = (u64*)(g_Xagg + (size_t)b * KTOT);
    const u64* redp = (const u64*)red;
    for (int i = tid; i < 1152; i += 512) {
        u64 v = redp[i];
        #pragma unroll
        for (int gg = 1; gg < 8; gg++) v = fadd2(v, redp[gg * 1152 + i]);
        dstrow[i] = v;
    }
    if (tid < 128)
        g_Xagg[(size_t)b * KTOT + 2304 + tid] = hv;
}

// ---------------------------------------------------------------------------
// K2: per-slice GEMM + last-arrival epilogue (fold 19 partials + sigmoid).
//   grid = (8 n-tiles, 19 slices), 512 threads = 4 K-quarters x 128 rows.
//   A staged to smem (coalesced LDG, XOR-swizzled STS/LDS). After writing its
//   partial, each block arrives on a monotonic per-ntile counter; the 19th
//   arrival folds all 19 slices for this ntile and applies sigmoid. No k3.
// ---------------------------------------------------------------------------
#define K2_SMEM (65536 + 8192)
__global__ __launch_bounds__(512, 1)
void k2_gemm(const float* __restrict__ tw,   // [9][128][128]
             const float* __restrict__ dw,   // [9][128][128]
             const float* __restrict__ hw,   // [128][128]
             float* __restrict__ out)        // [B][128]
{
    extern __shared__ __align__(16) char smraw2[];
    float* As = (float*)smraw2;                // [k][b^(k&31)]
    float* Ws = (float*)(smraw2 + 65536);      // [k][16]
    __shared__ unsigned s_last;

    const int ntile = blockIdx.x;
    const int ks    = blockIdx.y;
    const int tid   = threadIdx.x;
    const int row   = tid & 127;    // batch row
    const int kq    = tid >> 7;     // K quarter (0..3)
    const int j0    = ntile * 16;

    const float* Wsrc;
    if (ks < 9)       Wsrc = tw + (size_t)ks * 16384;
    else if (ks < 18) Wsrc = dw + (size_t)(ks - 9) * 16384;
    else              Wsrc = hw;

    // stage W tile [128][16]
    {
        int k = tid >> 2, jo = (tid & 3) * 4;
        *(float4*)(Ws + k * 16 + jo) =
            *(const float4*)(Wsrc + k * 128 + j0 + jo);
    }
    // stage full A slice [128k][128b], XOR-swizzled (conflict-free STS+LDS)
    {
        const float* Abase = g_Xagg + ks * 128;
        #pragma unroll
        for (int i = 0; i < 32; i++) {
            int idx = i * 512 + tid;
            int kf = idx & 127;      // lanes -> consecutive k (coalesced LDG)
            int bb = idx >> 7;
            As[kf * 128 + (bb ^ (kf & 31))] = Abase[(size_t)bb * KTOT + kf];
        }
    }
    __syncthreads();

    u64 acc[8];
    #pragma unroll
    for (int i = 0; i < 8; i++) acc[i] = 0ull;

    #pragma unroll 8
    for (int kk = 0; kk < 32; kk++) {
        int k = kq * 32 + kk;
        u64 a2 = pack2(As[k * 128 + (row ^ kk)]);       // LDS.32 cf
        const double2* w = (const double2*)(Ws + k * 16);
        double2 w0 = w[0], w1 = w[1], w2 = w[2], w3 = w[3]; // LDS.128 bcast
        ffma2(acc[0], a2, __double_as_longlong(w0.x));
        ffma2(acc[1], a2, __double_as_longlong(w0.y));
        ffma2(acc[2], a2, __double_as_longlong(w1.x));
        ffma2(acc[3], a2, __double_as_longlong(w1.y));
        ffma2(acc[4], a2, __double_as_longlong(w2.x));
        ffma2(acc[5], a2, __double_as_longlong(w2.y));
        ffma2(acc[6], a2, __double_as_longlong(w3.x));
        ffma2(acc[7], a2, __double_as_longlong(w3.y));
    }

    // combine 4 K-quarters (Cs aliases As after mainloop)
    __syncthreads();
    u64* Cs = (u64*)As;
    if (kq > 0) {
        u64* cdst = Cs + ((kq - 1) * 128 + row) * 8;
        #pragma unroll
        for (int i = 0; i < 8; i++) cdst[i] = acc[i];
    }
    __syncthreads();
    if (kq == 0) {
        u64* dst = (u64*)(g_gpart + ((size_t)ks * BATCH + row) * HID + j0);
        #pragma unroll
        for (int i = 0; i < 8; i++) {
            u64 v = acc[i];
            v = fadd2(v, Cs[(0 * 128 + row) * 8 + i]);
            v = fadd2(v, Cs[(1 * 128 + row) * 8 + i]);
            v = fadd2(v, Cs[(2 * 128 + row) * 8 + i]);
            dst[i] = v;
        }
    }

    // ---- arrival: last block for this ntile folds + sigmoids --------------
    __threadfence();             // make this block's partial visible gpu-wide
    __syncthreads();
    if (tid == 0) {
        unsigned prev = atomicAdd(&g_tilecnt[ntile], 1u);  // monotonic
        s_last = ((prev % KSLICES) == (KSLICES - 1)) ? 1u : 0u;
    }
    __syncthreads();

    if (s_last) {
        __threadfence();         // acquire side: order reads after arrivals
        int b  = tid >> 2;               // 0..127
        int jo = (tid & 3) * 4;          // 0,4,8,12
        const float* src = g_gpart + (size_t)b * HID + j0 + jo;
        float4 v = make_float4(0.f, 0.f, 0.f, 0.f);
        #pragma unroll
        for (int s = 0; s < KSLICES; s++) {
            float4 p = *(const float4*)(src + (size_t)s * (BATCH * HID));
            v.x += p.x; v.y += p.y; v.z += p.z; v.w += p.w;
        }
        float4 r;
        r.x = 1.0f / (1.0f + expf(-v.x));
        r.y = 1.0f / (1.0f + expf(-v.y));
        r.z = 1.0f / (1.0f + expf(-v.z));
        r.w = 1.0f / (1.0f + expf(-v.w));
        *(float4*)(out + (size_t)b * HID + j0 + jo) = r;
    }
}

// ---------------------------------------------------------------------------
extern "C" void kernel_launch(void* const* d_in, const int* in_sizes, int n_in,
                              void* d_out, int out_size)
{
    const float* x    = (const float*)d_in[0];
    const int*   tc   = (const int*)  d_in[1];
    const int*   dc   = (const int*)  d_in[2];
    const void*  mask = (const void*) d_in[3];
    const float* h    = (const float*)d_in[4];
    const float* tw   = (const float*)d_in[5];
    const float* dw   = (const float*)d_in[6];
    const float* hw   = (const float*)d_in[7];
    float* out = (float*)d_out;

    static int attr_done = 0;
    if (!attr_done) {
        cudaFuncSetAttribute(k1_aggregate,
                             cudaFuncAttributeMaxDynamicSharedMemorySize, K1_SMEM);
        cudaFuncSetAttribute(k2_gemm,
                             cudaFuncAttributeMaxDynamicSharedMemorySize, K2_SMEM);
        attr_done = 1;
    }

    k1_aggregate<<<BATCH, 512, K1_SMEM>>>(x, tc, dc, mask, h);
    dim3 g2(8, KSLICES);
    k2_gemm<<<g2, 512, K2_SMEM>>>(tw, dw, hw, out);
}

// round 10
// speedup vs baseline: 1.4093x; 1.4093x over previous
#include <cuda_runtime.h>
#include <math.h>

#define BATCH 128
#define CTX 64
#define HID 128
#define KSLICES 19            // 9 time + 9 dist + 1 hidden
#define KTOT (KSLICES*128)    // 2432
#define KGROUPS 16
#define KG 152                // KTOT / KGROUPS

typedef unsigned long long u64;

// Scratch (__device__ globals: allocation-free rule)
__device__ float g_Xagg[BATCH * KTOT];             // [b][k] row-major
__device__ float g_gpart[KGROUPS * BATCH * HID];   // per-kgroup GEMM partials

// ---- packed f32x2 helpers --------------------------------------------------
__device__ __forceinline__ u64 pack2(float v) {
    u64 r; asm("mov.b64 %0, {%1, %1};" : "=l"(r) : "f"(v)); return r;
}
__device__ __forceinline__ void ffma2(u64& d, u64 a, u64 b) {
    asm("fma.rn.f32x2 %0, %1, %2, %0;" : "+l"(d) : "l"(a), "l"(b));
}
__device__ __forceinline__ u64 fadd2(u64 a, u64 b) {
    u64 r; asm("add.rn.f32x2 %0, %1, %2;" : "=l"(r) : "l"(a), "l"(b)); return r;
}

// ---------------------------------------------------------------------------
// K1: per-batch slot aggregation  acc[18][128] = sel[18][64] @ x[64][128]
//   grid = 128 (batch), 512 threads = 8 ctx-groups x 64 dim-pairs.
//   dynamic smem: sel2 9216B + red[8] 73728B = 82944B. Coalesced [b][k] store.
// ---------------------------------------------------------------------------
#define K1_SMEM (9216 + 73728)
__global__ __launch_bounds__(512, 1)
void k1_aggregate(const float* __restrict__ x,     // [B][CTX][128]
                  const int* __restrict__ timec,   // [B][CTX]
                  const int* __restrict__ distc,   // [B][CTX]
                  const void* __restrict__ maskp,  // [B][CTX] int32 OR bytes
                  const float* __restrict__ h)     // [B][128]
{
    extern __shared__ __align__(16) char smraw[];
    u64*   sel2 = (u64*)smraw;                 // [c][s] : c*18+s
    float* red  = (float*)(smraw + 9216);      // [g][i] : g*2304+i
    __shared__ int s_flag;

    const int b   = blockIdx.x;
    const int tid = threadIdx.x;
    const int g   = tid >> 6;   // ctx group: c in [8g, 8g+8)
    const int q   = tid & 63;   // dim pair:  dims 2q, 2q+1

    // ---- front-issue ALL global loads (one latency round trip) ----
    u64 xv[8];
    {
        const float* xb = x + (size_t)b * CTX * 128 + q * 2;
        #pragma unroll
        for (int cc = 0; cc < 8; cc++)
            xv[cc] = *(const u64*)(xb + (g * 8 + cc) * 128);
    }
    unsigned sniffw = ((const unsigned*)maskp)[tid];   // dtype sniff
    int t_ = 0, d_ = 0; unsigned m_int = 0; unsigned char m_byte = 0;
    float hv = 0.0f;
    if (tid < 128) {
        int c = tid & 63;
        t_ = timec[b * CTX + c];
        d_ = distc[b * CTX + c];
        m_int  = ((const unsigned*)maskp)[b * CTX + c];
        m_byte = ((const unsigned char*)maskp)[b * CTX + c];
        hv = h[b * HID + tid];
    }

    if (tid == 0) s_flag = 0;
    __syncthreads();
    if (sniffw > 1u) atomicOr(&s_flag, 1);
    __syncthreads();
    const int byte_layout = s_flag;

    if (tid < 128) {
        int c = tid & 63, hf = tid >> 6;
        int m = byte_layout ? (m_byte != 0) : (m_int != 0);
        float w = m ? 0.5f : 0.0f;
        int idx = hf ? d_ : t_;
        u64 wp = pack2(w);
        #pragma unroll
        for (int s = 0; s < 9; s++)
            sel2[c * 18 + hf * 9 + s] = (idx == s) ? wp : 0ull;
    }
    __syncthreads();

    u64 acc[18];
    #pragma unroll
    for (int s = 0; s < 18; s++) acc[s] = 0ull;

    #pragma unroll
    for (int cc = 0; cc < 8; cc++) {
        int c = g * 8 + cc;
        u64 xc = xv[cc];
        #pragma unroll
        for (int s = 0; s < 18; s++)
            ffma2(acc[s], sel2[c * 18 + s], xc);   // LDS.64 bcast + FFMA2
    }

    #pragma unroll
    for (int s = 0; s < 18; s++)
        *(u64*)&red[g * 2304 + s * 128 + q * 2] = acc[s];
    __syncthreads();

    // fold 8 groups as u64 pairs, coalesced STG.64 into g_Xagg[b][k]
    u64* dstrow = (u64*)(g_Xagg + (size_t)b * KTOT);
    const u64* redp = (const u64*)red;
    for (int i = tid; i < 1152; i += 512) {
        u64 v = redp[i];
        #pragma unroll
        for (int gg = 1; gg < 8; gg++) v = fadd2(v, redp[gg * 1152 + i]);
        dstrow[i] = v;
    }
    if (tid < 128)
        g_Xagg[(size_t)b * KTOT + 2304 + tid] = hv;
}

// ---------------------------------------------------------------------------
// K2: balanced split-K GEMM.
//   grid = (8 n-tiles, 16 K-groups) = 128 blocks (one wave, no stragglers).
//   Each block: K-group of 152 consecutive k's x 16 cols, 512 thr = 4kq x 128row.
//   dynamic smem: As[152][128] swizzled 77824B + Ws[152][16] 9728B = 87552B.
// ---------------------------------------------------------------------------
#define K2_SMEM (152*128*4 + 152*16*4)
__global__ __launch_bounds__(512, 1)
void k2_gemm(const float* __restrict__ tw,   // [9][128][128]
             const float* __restrict__ dw,   // [9][128][128]
             const float* __restrict__ hw)   // [128][128]
{
    extern __shared__ __align__(16) char smraw2[];
    float* As = (float*)smraw2;                     // [r][b^(r&31)]
    float* Ws = (float*)(smraw2 + 152 * 128 * 4);   // [r][16]

    const int ntile = blockIdx.x;
    const int kg    = blockIdx.y;
    const int tid   = threadIdx.x;
    const int row   = tid & 127;    // batch row
    const int kq    = tid >> 7;     // K quarter (38 k's each)
    const int j0    = ntile * 16;
    const int g0    = kg * KG;      // global k base

    // stage W rows [152][16]: slice resolved per row
    for (int idx = tid; idx < KG * 4; idx += 512) {
        int r  = idx >> 2;
        int jo = (idx & 3) * 4;
        int kglob = g0 + r;
        int slice = kglob >> 7, krow = kglob & 127;
        const float* Wsrc;
        if (slice < 9)       Wsrc = tw + (size_t)slice * 16384;
        else if (slice < 18) Wsrc = dw + (size_t)(slice - 9) * 16384;
        else                 Wsrc = hw;
        *(float4*)(Ws + r * 16 + jo) =
            *(const float4*)(Wsrc + krow * 128 + j0 + jo);
    }
    // stage A block [152 r][128 b], XOR-swizzled (coalesced LDG, cf STS/LDS)
    {
        #pragma unroll
        for (int i = 0; i < 38; i++) {
            int idx = i * 512 + tid;          // 0..19455
            int bb = idx / KG;
            int r  = idx - bb * KG;           // consecutive per tid -> coalesced
            As[r * 128 + (bb ^ (r & 31))] =
                g_Xagg[(size_t)bb * KTOT + g0 + r];
        }
    }
    __syncthreads();

    u64 acc[8];
    #pragma unroll
    for (int i = 0; i < 8; i++) acc[i] = 0ull;

    const int rbase = kq * 38;
    #pragma unroll 19
    for (int t = 0; t < 38; t++) {
        int r = rbase + t;
        u64 a2 = pack2(As[r * 128 + (row ^ (r & 31))]);   // LDS.32 cf
        const double2* w = (const double2*)(Ws + r * 16);
        double2 w0 = w[0], w1 = w[1], w2 = w[2], w3 = w[3]; // LDS.128 bcast
        ffma2(acc[0], a2, __double_as_longlong(w0.x));
        ffma2(acc[1], a2, __double_as_longlong(w0.y));
        ffma2(acc[2], a2, __double_as_longlong(w1.x));
        ffma2(acc[3], a2, __double_as_longlong(w1.y));
        ffma2(acc[4], a2, __double_as_longlong(w2.x));
        ffma2(acc[5], a2, __double_as_longlong(w2.y));
        ffma2(acc[6], a2, __double_as_longlong(w3.x));
        ffma2(acc[7], a2, __double_as_longlong(w3.y));
    }

    // combine 4 K-quarters (Cs aliases As after mainloop)
    __syncthreads();
    u64* Cs = (u64*)As;
    if (kq > 0) {
        u64* cdst = Cs + ((kq - 1) * 128 + row) * 8;
        #pragma unroll
        for (int i = 0; i < 8; i++) cdst[i] = acc[i];
    }
    __syncthreads();
    if (kq == 0) {
        u64* dst = (u64*)(g_gpart + ((size_t)kg * BATCH + row) * HID + j0);
        #pragma unroll
        for (int i = 0; i < 8; i++) {
            u64 v = acc[i];
            v = fadd2(v, Cs[(0 * 128 + row) * 8 + i]);
            v = fadd2(v, Cs[(1 * 128 + row) * 8 + i]);
            v = fadd2(v, Cs[(2 * 128 + row) * 8 + i]);
            dst[i] = v;
        }
    }
}

// ---------------------------------------------------------------------------
// K3: fold 16 kgroup partials + sigmoid
// ---------------------------------------------------------------------------
__global__ __launch_bounds__(512)
void k3_sigmoid(float* __restrict__ out)
{
    int i = blockIdx.x * 512 + threadIdx.x;   // 16384 threads
    float v = 0.0f;
    #pragma unroll
    for (int kg = 0; kg < KGROUPS; kg++)
        v += g_gpart[kg * (BATCH * HID) + i];
    out[i] = 1.0f / (1.0f + expf(-v));
}

// ---------------------------------------------------------------------------
extern "C" void kernel_launch(void* const* d_in, const int* in_sizes, int n_in,
                              void* d_out, int out_size)
{
    const float* x    = (const float*)d_in[0];
    const int*   tc   = (const int*)  d_in[1];
    const int*   dc   = (const int*)  d_in[2];
    const void*  mask = (const void*) d_in[3];
    const float* h    = (const float*)d_in[4];
    const float* tw   = (const float*)d_in[5];
    const float* dw   = (const float*)d_in[6];
    const float* hw   = (const float*)d_in[7];
    float* out = (float*)d_out;

    static int attr_done = 0;
    if (!attr_done) {
        cudaFuncSetAttribute(k1_aggregate,
                             cudaFuncAttributeMaxDynamicSharedMemorySize, K1_SMEM);
        cudaFuncSetAttribute(k2_gemm,
                             cudaFuncAttributeMaxDynamicSharedMemorySize, K2_SMEM);
        attr_done = 1;
    }

    k1_aggregate<<<BATCH, 512, K1_SMEM>>>(x, tc, dc, mask, h);
    dim3 g2(8, KGROUPS);
    k2_gemm<<<g2, 512, K2_SMEM>>>(tw, dw, hw);
    k3_sigmoid<<<BATCH * HID / 512, 512>>>(out);
}